// round 1
// baseline (speedup 1.0000x reference)
#include <cuda_runtime.h>
#include <math.h>

#define BB 8
#define HH_ 128
#define WW_ 128
#define CH 64
#define OC 64
#define NCAC 128
#define KTOT 640
#define PIX 32
#define USTR 644
#define THREADS 256

// c2 context vector, produced by ctx_kernel, consumed by nca_kernel
__device__ float g_c2[BB * OC];

// ---------------------------------------------------------------------------
// Kernel A: attention (collapsed) + LayerNorm -> c2   [tiny: 8x64]
// attended == v = c@Wv + bv  (softmax pooling of a spatially-constant value
// cancels exactly). a = LN(v@Wo + bo + c); c2 = c + a.
// ---------------------------------------------------------------------------
__global__ void ctx_kernel(const float* __restrict__ c,
                           const float* __restrict__ Wv, const float* __restrict__ bv,
                           const float* __restrict__ Wo, const float* __restrict__ bo,
                           const float* __restrict__ lng, const float* __restrict__ lnb,
                           float* __restrict__ outc2)
{
    __shared__ float sv[BB][OC];
    __shared__ float st[BB][OC];
    int b = threadIdx.x >> 5;
    int lane = threadIdx.x & 31;

    #pragma unroll
    for (int oo = 0; oo < 2; oo++) {
        int o = lane + 32 * oo;
        float acc = bv[o];
        #pragma unroll 8
        for (int i = 0; i < OC; i++) acc += c[b * OC + i] * Wv[i * OC + o];
        sv[b][o] = acc;
    }
    __syncwarp();
    #pragma unroll
    for (int oo = 0; oo < 2; oo++) {
        int o = lane + 32 * oo;
        float acc = bo[o] + c[b * OC + o];
        #pragma unroll 8
        for (int i = 0; i < OC; i++) acc += sv[b][i] * Wo[i * OC + o];
        st[b][o] = acc;
    }
    __syncwarp();
    float t0 = st[b][lane], t1 = st[b][lane + 32];
    float s = t0 + t1;
    #pragma unroll
    for (int off = 16; off; off >>= 1) s += __shfl_xor_sync(0xffffffffu, s, off);
    float m = s * (1.0f / 64.0f);
    float d0 = t0 - m, d1 = t1 - m;
    float q = d0 * d0 + d1 * d1;
    #pragma unroll
    for (int off = 16; off; off >>= 1) q += __shfl_xor_sync(0xffffffffu, q, off);
    float inv = rsqrtf(q * (1.0f / 64.0f) + 1e-5f);
    #pragma unroll
    for (int oo = 0; oo < 2; oo++) {
        int o = lane + 32 * oo;
        float a = (st[b][o] - m) * inv * lng[o] + lnb[o];
        float v2 = c[b * OC + o] + a;
        g_c2[b * OC + o] = v2;
        outc2[b * OC + o] = v2;
    }
}

// ---------------------------------------------------------------------------
// Kernel B: fused NCA perception (4 dilated depthwise convs, context half
// via masked kernel-sums) + update MLP (640->64 GELU 64->64).
// Block = 32 pixels of one row. smem: U[32][644] + (pk | W-chunk + H).
// ---------------------------------------------------------------------------
#define SMEM_FLOATS (PIX * USTR + 4096 + PIX * 68)
#define SMEM_BYTES  (SMEM_FLOATS * 4)

__global__ __launch_bounds__(256, 2)
void nca_kernel(const float* __restrict__ x, const float* __restrict__ pk,
                const float* __restrict__ W1, const float* __restrict__ b1,
                const float* __restrict__ W2, const float* __restrict__ b2,
                float* __restrict__ y)
{
    extern __shared__ float smem[];
    float* sU  = smem;                    // [32][644]
    float* sPK = smem + PIX * USTR;       // 4608 floats   (phase 1)
    float* sC2 = sPK + 4608;              // 64 floats     (phase 1)
    float* sW  = smem + PIX * USTR;       // 4096 floats   (phase 2/3, aliases sPK)
    float* sH  = sW + 4096;               // [32][68]      (phase 3)

    int tid = threadIdx.x;
    int bi = blockIdx.x;
    int w0 = (bi & 3) << 5;
    int h  = (bi >> 2) & 127;
    int b  = bi >> 9;

    // stage pk + c2
    for (int r = tid; r < 4608; r += THREADS) sPK[r] = pk[r];
    if (tid < 64) sC2[tid] = g_c2[b * 64 + tid];
    __syncthreads();

    // ---- phase 1: build U[p][0..639] ----
    for (int p = 0; p < PIX; p++) {
        int w = w0 + p;
        const float* xpix = x + ((size_t)(((b << 7) + h) << 7) + w) * 64;
        for (int kcol = tid; kcol < KTOT; kcol += THREADS) {
            float val;
            if (kcol < 64) {
                val = xpix[kcol];
            } else if (kcol < 128) {
                val = sC2[kcol - 64];
            } else {
                int i  = (kcol - 128) >> 7;      // dilation index: d = 1<<i
                int ch = (kcol - 128) & 127;
                int d  = 1 << i;
                const float* pkp = sPK + (i * 128 + ch) * 9;
                if (ch < 64) {
                    float acc = 0.f;
                    #pragma unroll
                    for (int dy = -1; dy <= 1; dy++) {
                        int hh = h + dy * d;
                        if ((unsigned)hh < 128u) {
                            const float* xr = x + ((size_t)(((b << 7) + hh) << 7)) * 64 + ch;
                            #pragma unroll
                            for (int dx = -1; dx <= 1; dx++) {
                                int ww = w + dx * d;
                                if ((unsigned)ww < 128u)
                                    acc += xr[(size_t)ww << 6] * pkp[(dy + 1) * 3 + (dx + 1)];
                            }
                        }
                    }
                    val = acc;
                } else {
                    // context half: conv of constant field = c2 * in-bounds tap sum
                    float ks = 0.f;
                    #pragma unroll
                    for (int dy = -1; dy <= 1; dy++) {
                        int hh = h + dy * d;
                        if ((unsigned)hh < 128u) {
                            #pragma unroll
                            for (int dx = -1; dx <= 1; dx++) {
                                int ww = w + dx * d;
                                if ((unsigned)ww < 128u) ks += pkp[(dy + 1) * 3 + (dx + 1)];
                            }
                        }
                    }
                    val = sC2[ch - 64] * ks;
                }
            }
            sU[p * USTR + kcol] = val;
        }
    }
    __syncthreads();

    // ---- phase 2: hidden = U @ W1 + b1 (chunked over K) ----
    int p  = tid >> 3;      // pixel 0..31
    int jg = tid & 7;       // hidden-channel group: j = jg*8 .. jg*8+7
    float acc[8];
    #pragma unroll
    for (int q = 0; q < 8; q++) acc[q] = b1[jg * 8 + q];
    const float* up = sU + p * USTR;

    for (int kc = 0; kc < KTOT; kc += 64) {
        __syncthreads();
        {   // stage W1[kc..kc+64)[:] -> sW (4096 floats)
            const float4* src = (const float4*)(W1 + kc * 64);
            float4* dst = (float4*)sW;
            for (int r = tid; r < 1024; r += THREADS) dst[r] = src[r];
        }
        __syncthreads();
        #pragma unroll 16
        for (int k = 0; k < 64; k++) {
            float u = up[kc + k];
            float4 wa = *(const float4*)(sW + k * 64 + jg * 8);
            float4 wb = *(const float4*)(sW + k * 64 + jg * 8 + 4);
            acc[0] += u * wa.x; acc[1] += u * wa.y; acc[2] += u * wa.z; acc[3] += u * wa.w;
            acc[4] += u * wb.x; acc[5] += u * wb.y; acc[6] += u * wb.z; acc[7] += u * wb.w;
        }
    }
    __syncthreads();

    // ---- phase 3: exact GELU, then y = H @ W2 + b2 ----
    #pragma unroll
    for (int q = 0; q < 8; q++) {
        float hv = acc[q];
        sH[p * 68 + jg * 8 + q] = 0.5f * hv * (1.0f + erff(hv * 0.70710678118654752440f));
    }
    __syncthreads();
    {   // stage W2 -> sW
        const float4* src = (const float4*)W2;
        float4* dst = (float4*)sW;
        for (int r = tid; r < 1024; r += THREADS) dst[r] = src[r];
    }
    __syncthreads();

    float acc2[8];
    #pragma unroll
    for (int q = 0; q < 8; q++) acc2[q] = b2[jg * 8 + q];
    const float* hp = sH + p * 68;
    #pragma unroll 16
    for (int j = 0; j < 64; j++) {
        float hv = hp[j];
        float4 wa = *(const float4*)(sW + j * 64 + jg * 8);
        float4 wb = *(const float4*)(sW + j * 64 + jg * 8 + 4);
        acc2[0] += hv * wa.x; acc2[1] += hv * wa.y; acc2[2] += hv * wa.z; acc2[3] += hv * wa.w;
        acc2[4] += hv * wb.x; acc2[5] += hv * wb.y; acc2[6] += hv * wb.z; acc2[7] += hv * wb.w;
    }
    float* yp = y + ((size_t)(((b << 7) + h) << 7) + (w0 + p)) * 64 + jg * 8;
    *(float4*)yp       = make_float4(acc2[0], acc2[1], acc2[2], acc2[3]);
    *(float4*)(yp + 4) = make_float4(acc2[4], acc2[5], acc2[6], acc2[7]);
}

// ---------------------------------------------------------------------------
// Launch. Input order (metadata): x, c, Wq, bq, Wk, bk, Wv, bv, Wo, bo,
// ln_g, ln_b, pk, W1, b1, W2, b2.  Output: y [8,128,128,64] then c2 [8,64].
// ---------------------------------------------------------------------------
extern "C" void kernel_launch(void* const* d_in, const int* in_sizes, int n_in,
                              void* d_out, int out_size)
{
    const float* x   = (const float*)d_in[0];
    const float* c   = (const float*)d_in[1];
    const float* Wv  = (const float*)d_in[6];
    const float* bv  = (const float*)d_in[7];
    const float* Wo  = (const float*)d_in[8];
    const float* bo  = (const float*)d_in[9];
    const float* lng = (const float*)d_in[10];
    const float* lnb = (const float*)d_in[11];
    const float* pk  = (const float*)d_in[12];
    const float* W1  = (const float*)d_in[13];
    const float* b1  = (const float*)d_in[14];
    const float* W2  = (const float*)d_in[15];
    const float* b2  = (const float*)d_in[16];

    float* y     = (float*)d_out;
    float* outc2 = y + (size_t)BB * HH_ * WW_ * CH;

    ctx_kernel<<<1, 256>>>(c, Wv, bv, Wo, bo, lng, lnb, outc2);

    cudaFuncSetAttribute(nca_kernel, cudaFuncAttributeMaxDynamicSharedMemorySize, SMEM_BYTES);
    nca_kernel<<<BB * HH_ * (WW_ / PIX), THREADS, SMEM_BYTES>>>(x, pk, W1, b1, W2, b2, y);
}

// round 2
// speedup vs baseline: 1.8145x; 1.8145x over previous
#include <cuda_runtime.h>
#include <math.h>

#define BB 8
#define HH_ 128
#define WW_ 128
#define CH 64
#define OC 64
#define KTOT 640
#define PIX 32
#define USTR 644      // == 4 (mod 32)  -> conflict-free A-frag LDS
#define WSTR 72       // == 8 (mod 32)  -> conflict-free B-frag LDS
#define HSTR 68       // == 4 (mod 32)
#define THREADS 256

// smem layout (floats)
#define OFF_U    0
#define OFF_WHI  (PIX * USTR)              // 20608
#define OFF_WLO  (OFF_WHI + 32 * WSTR)     // +2304
#define OFF_H    (OFF_WHI + 2 * 32 * WSTR) // 25216
#define OFF_C2   (OFF_H + PIX * HSTR)      // 27392
#define SMEM_FLOATS (OFF_C2 + 64)          // 27456
#define SMEM_BYTES  (SMEM_FLOATS * 4)      // 109824

__device__ float g_c2[BB * OC];

// ---------------------------------------------------------------------------
// Kernel A: attention collapses analytically (softmax pooling of a constant
// value field == the value itself). c2 = c + LN(v@Wo + bo + c).
// ---------------------------------------------------------------------------
__global__ void ctx_kernel(const float* __restrict__ c,
                           const float* __restrict__ Wv, const float* __restrict__ bv,
                           const float* __restrict__ Wo, const float* __restrict__ bo,
                           const float* __restrict__ lng, const float* __restrict__ lnb,
                           float* __restrict__ outc2)
{
    __shared__ float sv[BB][OC];
    __shared__ float st[BB][OC];
    int b = threadIdx.x >> 5;
    int lane = threadIdx.x & 31;

    #pragma unroll
    for (int oo = 0; oo < 2; oo++) {
        int o = lane + 32 * oo;
        float acc = bv[o];
        #pragma unroll 8
        for (int i = 0; i < OC; i++) acc += c[b * OC + i] * Wv[i * OC + o];
        sv[b][o] = acc;
    }
    __syncwarp();
    #pragma unroll
    for (int oo = 0; oo < 2; oo++) {
        int o = lane + 32 * oo;
        float acc = bo[o] + c[b * OC + o];
        #pragma unroll 8
        for (int i = 0; i < OC; i++) acc += sv[b][i] * Wo[i * OC + o];
        st[b][o] = acc;
    }
    __syncwarp();
    float t0 = st[b][lane], t1 = st[b][lane + 32];
    float s = t0 + t1;
    #pragma unroll
    for (int off = 16; off; off >>= 1) s += __shfl_xor_sync(0xffffffffu, s, off);
    float m = s * (1.0f / 64.0f);
    float d0 = t0 - m, d1 = t1 - m;
    float q = d0 * d0 + d1 * d1;
    #pragma unroll
    for (int off = 16; off; off >>= 1) q += __shfl_xor_sync(0xffffffffu, q, off);
    float inv = rsqrtf(q * (1.0f / 64.0f) + 1e-5f);
    #pragma unroll
    for (int oo = 0; oo < 2; oo++) {
        int o = lane + 32 * oo;
        float a = (st[b][o] - m) * inv * lng[o] + lnb[o];
        float v2 = c[b * OC + o] + a;
        g_c2[b * OC + o] = v2;
        outc2[b * OC + o] = v2;
    }
}

// ---------------------------------------------------------------------------
// tf32 helpers
// ---------------------------------------------------------------------------
__device__ __forceinline__ unsigned f2tf(float v) {
    unsigned r;
    asm("cvt.rna.tf32.f32 %0, %1;" : "=r"(r) : "f"(v));
    return r;
}

__device__ __forceinline__ void mma_tf32(float* c,
                                         unsigned a0, unsigned a1, unsigned a2, unsigned a3,
                                         unsigned b0, unsigned b1)
{
    asm volatile(
        "mma.sync.aligned.m16n8k8.row.col.f32.tf32.tf32.f32 "
        "{%0,%1,%2,%3}, {%4,%5,%6,%7}, {%8,%9}, {%0,%1,%2,%3};"
        : "+f"(c[0]), "+f"(c[1]), "+f"(c[2]), "+f"(c[3])
        : "r"(a0), "r"(a1), "r"(a2), "r"(a3), "r"(b0), "r"(b1));
}

// ---------------------------------------------------------------------------
// Kernel B: fused perception + MLP. Phase 1 builds U[32][640] in smem (f32),
// phase 2 = 3xTF32 tensor-core GEMM U@W1 (+b1, GELU) -> H, phase 3 = H@W2+b2.
// ---------------------------------------------------------------------------
__global__ __launch_bounds__(256, 2)
void nca_kernel(const float* __restrict__ x, const float* __restrict__ pk,
                const float* __restrict__ W1, const float* __restrict__ b1,
                const float* __restrict__ W2, const float* __restrict__ b2,
                float* __restrict__ y)
{
    extern __shared__ float smem[];
    float* sU   = smem + OFF_U;
    float* sWhi = smem + OFF_WHI;
    float* sWlo = smem + OFF_WLO;
    float* sH   = smem + OFF_H;
    float* sC2  = smem + OFF_C2;
    float* sPK  = smem + OFF_WHI;   // phase-1 alias (4608 floats == hi+lo region)

    int tid = threadIdx.x;
    int bi = blockIdx.x;
    int w0 = (bi & 3) << 5;
    int h  = (bi >> 2) & 127;
    int b  = bi >> 9;

    // stage pk + c2
    for (int r = tid; r < 4608; r += THREADS) sPK[r] = pk[r];
    if (tid < 64) sC2[tid] = g_c2[b * 64 + tid];
    __syncthreads();

    // ---- phase 1: build U[p][0..639] ----
    for (int p = 0; p < PIX; p++) {
        int w = w0 + p;
        const float* xpix = x + ((size_t)(((b << 7) + h) << 7) + w) * 64;
        for (int kcol = tid; kcol < KTOT; kcol += THREADS) {
            float val;
            if (kcol < 64) {
                val = xpix[kcol];
            } else if (kcol < 128) {
                val = sC2[kcol - 64];
            } else {
                int i  = (kcol - 128) >> 7;
                int ch = (kcol - 128) & 127;
                int d  = 1 << i;
                const float* pkp = sPK + (i * 128 + ch) * 9;
                if (ch < 64) {
                    float acc = 0.f;
                    #pragma unroll
                    for (int dy = -1; dy <= 1; dy++) {
                        int hh = h + dy * d;
                        if ((unsigned)hh < 128u) {
                            const float* xr = x + ((size_t)(((b << 7) + hh) << 7)) * 64 + ch;
                            #pragma unroll
                            for (int dx = -1; dx <= 1; dx++) {
                                int ww = w + dx * d;
                                if ((unsigned)ww < 128u)
                                    acc += xr[(size_t)ww << 6] * pkp[(dy + 1) * 3 + (dx + 1)];
                            }
                        }
                    }
                    val = acc;
                } else {
                    float ks = 0.f;
                    #pragma unroll
                    for (int dy = -1; dy <= 1; dy++) {
                        int hh = h + dy * d;
                        if ((unsigned)hh < 128u) {
                            #pragma unroll
                            for (int dx = -1; dx <= 1; dx++) {
                                int ww = w + dx * d;
                                if ((unsigned)ww < 128u) ks += pkp[(dy + 1) * 3 + (dx + 1)];
                            }
                        }
                    }
                    val = sC2[ch - 64] * ks;
                }
            }
            sU[p * USTR + kcol] = val;
        }
    }
    __syncthreads();

    // ---- warp/thread mapping for mma ----
    int warp = tid >> 5, lane = tid & 31;
    int g  = lane >> 2;     // 0..7
    int tg = lane & 3;      // 0..3
    int mh = warp & 1;      // 0..1 -> pixel rows m0..m0+15
    int nh = warp >> 1;     // 0..3 -> 16 output cols
    int m0 = mh << 4;
    int n0 = nh << 4;

    // ---- phase 2: H = GELU(U @ W1 + b1), 3xTF32 ----
    float acc[2][4] = {{0.f, 0.f, 0.f, 0.f}, {0.f, 0.f, 0.f, 0.f}};

    for (int kc = 0; kc < KTOT; kc += 32) {
        __syncthreads();
        // stage 32 K-rows of W1, pre-split hi/lo
        for (int i = tid; i < 2048; i += THREADS) {
            int r = i >> 6, cc = i & 63;
            float v = W1[(kc + r) * 64 + cc];
            unsigned hi = f2tf(v);
            float vlo = v - __uint_as_float(hi);
            sWhi[r * WSTR + cc] = __uint_as_float(hi);
            sWlo[r * WSTR + cc] = __uint_as_float(f2tf(vlo));
        }
        __syncthreads();

        #pragma unroll
        for (int ks = 0; ks < 4; ks++) {
            int k0 = ks << 3;
            // A fragment (f32 from sU, split in regs)
            float av0 = sU[(m0 + g) * USTR + kc + k0 + tg];
            float av1 = sU[(m0 + g + 8) * USTR + kc + k0 + tg];
            float av2 = sU[(m0 + g) * USTR + kc + k0 + tg + 4];
            float av3 = sU[(m0 + g + 8) * USTR + kc + k0 + tg + 4];
            unsigned ah0 = f2tf(av0), ah1 = f2tf(av1), ah2 = f2tf(av2), ah3 = f2tf(av3);
            unsigned al0 = f2tf(av0 - __uint_as_float(ah0));
            unsigned al1 = f2tf(av1 - __uint_as_float(ah1));
            unsigned al2 = f2tf(av2 - __uint_as_float(ah2));
            unsigned al3 = f2tf(av3 - __uint_as_float(ah3));

            #pragma unroll
            for (int nt = 0; nt < 2; nt++) {
                int ncol = n0 + (nt << 3) + g;
                unsigned bh0 = __float_as_uint(sWhi[(k0 + tg)     * WSTR + ncol]);
                unsigned bh1 = __float_as_uint(sWhi[(k0 + tg + 4) * WSTR + ncol]);
                unsigned bl0 = __float_as_uint(sWlo[(k0 + tg)     * WSTR + ncol]);
                unsigned bl1 = __float_as_uint(sWlo[(k0 + tg + 4) * WSTR + ncol]);
                mma_tf32(acc[nt], ah0, ah1, ah2, ah3, bh0, bh1);
                mma_tf32(acc[nt], ah0, ah1, ah2, ah3, bl0, bl1);
                mma_tf32(acc[nt], al0, al1, al2, al3, bh0, bh1);
            }
        }
    }

    // bias + exact GELU -> sH
    #pragma unroll
    for (int nt = 0; nt < 2; nt++) {
        #pragma unroll
        for (int e = 0; e < 4; e++) {
            int col = n0 + (nt << 3) + (tg << 1) + (e & 1);
            int row = m0 + g + ((e >> 1) << 3);
            float v = acc[nt][e] + b1[col];
            sH[row * HSTR + col] = 0.5f * v * (1.0f + erff(v * 0.70710678118654752440f));
        }
    }

    // ---- phase 3: y = H @ W2 + b2, 3xTF32 ----
    float acc2[2][4] = {{0.f, 0.f, 0.f, 0.f}, {0.f, 0.f, 0.f, 0.f}};

    for (int kc = 0; kc < 64; kc += 32) {
        __syncthreads();
        for (int i = tid; i < 2048; i += THREADS) {
            int r = i >> 6, cc = i & 63;
            float v = W2[(kc + r) * 64 + cc];
            unsigned hi = f2tf(v);
            float vlo = v - __uint_as_float(hi);
            sWhi[r * WSTR + cc] = __uint_as_float(hi);
            sWlo[r * WSTR + cc] = __uint_as_float(f2tf(vlo));
        }
        __syncthreads();

        #pragma unroll
        for (int ks = 0; ks < 4; ks++) {
            int k0 = ks << 3;
            float av0 = sH[(m0 + g) * HSTR + kc + k0 + tg];
            float av1 = sH[(m0 + g + 8) * HSTR + kc + k0 + tg];
            float av2 = sH[(m0 + g) * HSTR + kc + k0 + tg + 4];
            float av3 = sH[(m0 + g + 8) * HSTR + kc + k0 + tg + 4];
            unsigned ah0 = f2tf(av0), ah1 = f2tf(av1), ah2 = f2tf(av2), ah3 = f2tf(av3);
            unsigned al0 = f2tf(av0 - __uint_as_float(ah0));
            unsigned al1 = f2tf(av1 - __uint_as_float(ah1));
            unsigned al2 = f2tf(av2 - __uint_as_float(ah2));
            unsigned al3 = f2tf(av3 - __uint_as_float(ah3));

            #pragma unroll
            for (int nt = 0; nt < 2; nt++) {
                int ncol = n0 + (nt << 3) + g;
                unsigned bh0 = __float_as_uint(sWhi[(k0 + tg)     * WSTR + ncol]);
                unsigned bh1 = __float_as_uint(sWhi[(k0 + tg + 4) * WSTR + ncol]);
                unsigned bl0 = __float_as_uint(sWlo[(k0 + tg)     * WSTR + ncol]);
                unsigned bl1 = __float_as_uint(sWlo[(k0 + tg + 4) * WSTR + ncol]);
                mma_tf32(acc2[nt], ah0, ah1, ah2, ah3, bh0, bh1);
                mma_tf32(acc2[nt], ah0, ah1, ah2, ah3, bl0, bl1);
                mma_tf32(acc2[nt], al0, al1, al2, al3, bh0, bh1);
            }
        }
    }

    // bias + store y
    #pragma unroll
    for (int nt = 0; nt < 2; nt++) {
        int col = n0 + (nt << 3) + (tg << 1);
        float o0 = acc2[nt][0] + b2[col];
        float o1 = acc2[nt][1] + b2[col + 1];
        float o2 = acc2[nt][2] + b2[col];
        float o3 = acc2[nt][3] + b2[col + 1];
        int row0 = m0 + g;
        float* yp0 = y + ((size_t)(((b << 7) + h) << 7) + (w0 + row0)) * 64 + col;
        float* yp1 = y + ((size_t)(((b << 7) + h) << 7) + (w0 + row0 + 8)) * 64 + col;
        *(float2*)yp0 = make_float2(o0, o1);
        *(float2*)yp1 = make_float2(o2, o3);
    }
}

// ---------------------------------------------------------------------------
extern "C" void kernel_launch(void* const* d_in, const int* in_sizes, int n_in,
                              void* d_out, int out_size)
{
    const float* x   = (const float*)d_in[0];
    const float* c   = (const float*)d_in[1];
    const float* Wv  = (const float*)d_in[6];
    const float* bv  = (const float*)d_in[7];
    const float* Wo  = (const float*)d_in[8];
    const float* bo  = (const float*)d_in[9];
    const float* lng = (const float*)d_in[10];
    const float* lnb = (const float*)d_in[11];
    const float* pk  = (const float*)d_in[12];
    const float* W1  = (const float*)d_in[13];
    const float* b1  = (const float*)d_in[14];
    const float* W2  = (const float*)d_in[15];
    const float* b2  = (const float*)d_in[16];

    float* y     = (float*)d_out;
    float* outc2 = y + (size_t)BB * HH_ * WW_ * CH;

    ctx_kernel<<<1, 256>>>(c, Wv, bv, Wo, bo, lng, lnb, outc2);

    cudaFuncSetAttribute(nca_kernel, cudaFuncAttributeMaxDynamicSharedMemorySize, SMEM_BYTES);
    nca_kernel<<<BB * HH_ * (WW_ / PIX), THREADS, SMEM_BYTES>>>(x, pk, W1, b1, W2, b2, y);
}

// round 3
// speedup vs baseline: 5.6243x; 3.0997x over previous
#include <cuda_runtime.h>
#include <math.h>

#define BB 8
#define CH 64
#define OC 64
#define PIX 32
#define THREADS 256
#define USTR 324      // ==4 mod 32, conflict-free A-frag LDS
#define WSTR 72       // ==8 mod 32, conflict-free B-frag LDS
#define HSTR 36       // ==4 mod 32

// smem layout in uint32 units
#define OFF_UHI 0
#define OFF_ULO (32*USTR)             // 10368
#define OFF_W   (2*32*USTR)           // 20736
#define OFF_WHI OFF_W
#define OFF_WLO (OFF_W + 32*WSTR)     // 23040
#define OFF_H   (OFF_W + 2*32*WSTR)   // 25344
#define OFF_HHI OFF_H
#define OFF_HLO (OFF_H + 32*HSTR)     // 26496
#define OFF_C2  (OFF_H + 2*32*HSTR)   // 27648
#define SMEM_U32 (OFF_C2 + 64)        // 27712
#define SMEM_BYTES (SMEM_U32*4)       // 110848

__device__ float g_c2[BB*OC];
__device__ __align__(16) unsigned gW1hi[320*64];
__device__ __align__(16) unsigned gW1lo[320*64];
__device__ __align__(16) unsigned gW2hi[32*64];
__device__ __align__(16) unsigned gW2lo[32*64];

// pack two floats (even=k, odd=k+1) into bf16x2 hi + bf16x2 lo (residual)
__device__ __forceinline__ void bsplit(float e, float o, unsigned& ph, unsigned& pl) {
    asm("cvt.rn.bf16x2.f32 %0, %1, %2;" : "=r"(ph) : "f"(o), "f"(e));
    float eh = __uint_as_float(ph << 16);
    float oh = __uint_as_float(ph & 0xffff0000u);
    float el = e - eh, ol = o - oh;
    asm("cvt.rn.bf16x2.f32 %0, %1, %2;" : "=r"(pl) : "f"(ol), "f"(el));
}

__device__ __forceinline__ void mma_bf16(float* c,
                                         unsigned a0, unsigned a1, unsigned a2, unsigned a3,
                                         unsigned b0, unsigned b1)
{
    asm volatile(
        "mma.sync.aligned.m16n8k16.row.col.f32.bf16.bf16.f32 "
        "{%0,%1,%2,%3}, {%4,%5,%6,%7}, {%8,%9}, {%0,%1,%2,%3};"
        : "+f"(c[0]), "+f"(c[1]), "+f"(c[2]), "+f"(c[3])
        : "r"(a0), "r"(a1), "r"(a2), "r"(a3), "r"(b0), "r"(b1));
}

__device__ __forceinline__ float gelu(float v) {
    return 0.5f * v * (1.0f + erff(v * 0.70710678118654752440f));
}

// ---------------------------------------------------------------------------
// prep: split W1/W2 into packed bf16x2 hi/lo pair arrays (done once)
// ---------------------------------------------------------------------------
__global__ void prep_kernel(const float* __restrict__ W1, const float* __restrict__ W2)
{
    int t = blockIdx.x * THREADS + threadIdx.x;
    if (t < 320*64) {
        int pc = t >> 6, n = t & 63;
        unsigned ph, pl;
        bsplit(W1[(2*pc)*64 + n], W1[(2*pc+1)*64 + n], ph, pl);
        gW1hi[t] = ph; gW1lo[t] = pl;
    }
    if (t < 32*64) {
        int pc = t >> 6, n = t & 63;
        unsigned ph, pl;
        bsplit(W2[(2*pc)*64 + n], W2[(2*pc+1)*64 + n], ph, pl);
        gW2hi[t] = ph; gW2lo[t] = pl;
    }
}

// ---------------------------------------------------------------------------
// Attention collapses analytically: attended == v (softmax of constant value).
// c2 = c + LN(v@Wo + bo + c)
// ---------------------------------------------------------------------------
__global__ void ctx_kernel(const float* __restrict__ c,
                           const float* __restrict__ Wv, const float* __restrict__ bv,
                           const float* __restrict__ Wo, const float* __restrict__ bo,
                           const float* __restrict__ lng, const float* __restrict__ lnb,
                           float* __restrict__ outc2)
{
    __shared__ float sv[BB][OC];
    __shared__ float st[BB][OC];
    int b = threadIdx.x >> 5;
    int lane = threadIdx.x & 31;

    #pragma unroll
    for (int oo = 0; oo < 2; oo++) {
        int o = lane + 32*oo;
        float acc = bv[o];
        #pragma unroll 8
        for (int i = 0; i < OC; i++) acc += c[b*OC + i] * Wv[i*OC + o];
        sv[b][o] = acc;
    }
    __syncwarp();
    #pragma unroll
    for (int oo = 0; oo < 2; oo++) {
        int o = lane + 32*oo;
        float acc = bo[o] + c[b*OC + o];
        #pragma unroll 8
        for (int i = 0; i < OC; i++) acc += sv[b][i] * Wo[i*OC + o];
        st[b][o] = acc;
    }
    __syncwarp();
    float t0 = st[b][lane], t1 = st[b][lane + 32];
    float s = t0 + t1;
    #pragma unroll
    for (int off = 16; off; off >>= 1) s += __shfl_xor_sync(0xffffffffu, s, off);
    float m = s * (1.0f/64.0f);
    float d0 = t0 - m, d1 = t1 - m;
    float q = d0*d0 + d1*d1;
    #pragma unroll
    for (int off = 16; off; off >>= 1) q += __shfl_xor_sync(0xffffffffu, q, off);
    float inv = rsqrtf(q * (1.0f/64.0f) + 1e-5f);
    #pragma unroll
    for (int oo = 0; oo < 2; oo++) {
        int o = lane + 32*oo;
        float a = (st[b][o] - m) * inv * lng[o] + lnb[o];
        float v2 = c[b*OC + o] + a;
        g_c2[b*OC + o] = v2;
        outc2[b*OC + o] = v2;
    }
}

// ---------------------------------------------------------------------------
// Fused perception + MLP. All GEMM operands live in smem pre-packed bf16x2.
// ---------------------------------------------------------------------------
__global__ __launch_bounds__(256, 2)
void nca_kernel(const float* __restrict__ x, const float* __restrict__ pk,
                const float* __restrict__ b1, const float* __restrict__ b2,
                float* __restrict__ y)
{
    extern __shared__ unsigned smem[];
    unsigned* sUhi = smem + OFF_UHI;
    unsigned* sUlo = smem + OFF_ULO;
    unsigned* sWhi = smem + OFF_WHI;
    unsigned* sWlo = smem + OFF_WLO;
    unsigned* sHhi = smem + OFF_HHI;
    unsigned* sHlo = smem + OFF_HLO;
    float*    sC2f = (float*)(smem + OFF_C2);
    float*    sPK  = (float*)(smem + OFF_W);   // phase-1 alias over W region (4608 fl)

    int tid = threadIdx.x;
    int bi = blockIdx.x;
    int w0 = (bi & 3) << 5;
    int h  = (bi >> 2) & 127;
    int b  = bi >> 9;

    // stage pk + c2
    {
        const float4* src = (const float4*)pk;
        float4* dst = (float4*)sPK;
        for (int r = tid; r < 1152; r += THREADS) dst[r] = src[r];
        if (tid < 64) sC2f[tid] = g_c2[b*64 + tid];
    }
    __syncthreads();

    const size_t rowstride = 1u << 13;               // 128 px * 64 ch
    const size_t imgbase = ((size_t)(b << 7) + h) << 13;

    // ---- phase 1a: trivial pairs (x copy + c2 broadcast), pcs 0..63 ----
    #pragma unroll
    for (int j = 0; j < 8; j++) {
        int item = (j << 8) + tid;
        int pr = item & 63;
        int p  = item >> 6;
        float2 v;
        if (pr < 32) {
            v = *(const float2*)(x + imgbase + ((size_t)(w0 + p) << 6) + (pr << 1));
        } else {
            v = make_float2(sC2f[(pr - 32) << 1], sC2f[((pr - 32) << 1) + 1]);
        }
        unsigned ph, pl; bsplit(v.x, v.y, ph, pl);
        sUhi[p*USTR + pr] = ph; sUlo[p*USTR + pr] = pl;
    }

    // ---- phase 1b: context half (conv of constant = c2 * masked tap sums) ----
    {
        int cpair = tid >> 1, half = tid & 1;
        int di = cpair >> 5, cq = cpair & 31;
        int ch = 64 + (cq << 1);
        int d  = 1 << di;
        int pc = 96 + (di << 6) + cq;
        const float* tp0 = sPK + ((di << 7) + ch) * 9;
        float cs0[3] = {0.f,0.f,0.f}, cs1[3] = {0.f,0.f,0.f};
        #pragma unroll
        for (int t3 = 0; t3 < 3; t3++) {
            int hh = h + (t3 - 1) * d;
            if ((unsigned)hh < 128u) {
                #pragma unroll
                for (int dx = 0; dx < 3; dx++) {
                    cs0[dx] += tp0[t3*3 + dx];
                    cs1[dx] += tp0[9 + t3*3 + dx];
                }
            }
        }
        float c0 = sC2f[ch - 64], c1 = sC2f[ch - 63];
        #pragma unroll
        for (int j = 0; j < 16; j++) {
            int p = (j << 1) + half;
            int w = w0 + p;
            float k0 = 0.f, k1 = 0.f;
            #pragma unroll
            for (int dx = 0; dx < 3; dx++) {
                int ww = w + (dx - 1) * d;
                if ((unsigned)ww < 128u) { k0 += cs0[dx]; k1 += cs1[dx]; }
            }
            unsigned ph, pl; bsplit(c0*k0, c1*k1, ph, pl);
            sUhi[p*USTR + pc] = ph; sUlo[p*USTR + pc] = pl;
        }
    }

    // ---- phase 1c: real depthwise dilated conv, x half ----
    {
        int cpair = tid >> 1, half = tid & 1;
        int di = cpair >> 5, chp = cpair & 31;
        int ch = chp << 1;
        int d  = 1 << di;
        int pc = 64 + (di << 6) + chp;
        const float* tp0 = sPK + ((di << 7) + ch) * 9;
        float tap0[3][3], tap1[3][3];
        #pragma unroll
        for (int t3 = 0; t3 < 3; t3++)
            #pragma unroll
            for (int dx = 0; dx < 3; dx++) {
                tap0[t3][dx] = tp0[t3*3 + dx];
                tap1[t3][dx] = tp0[9 + t3*3 + dx];
            }
        const float* rp[3]; bool rv[3];
        #pragma unroll
        for (int t3 = 0; t3 < 3; t3++) {
            int hh = h + (t3 - 1) * d;
            rv[t3] = ((unsigned)hh < 128u);
            rp[t3] = x + (((size_t)(b << 7) + (hh & 127)) << 13) + ch;
        }
        #pragma unroll 4
        for (int j = 0; j < 16; j++) {
            int p = (j << 1) + half;
            int w = w0 + p;
            float a0 = 0.f, a1 = 0.f;
            #pragma unroll
            for (int t3 = 0; t3 < 3; t3++) {
                if (rv[t3]) {
                    #pragma unroll
                    for (int dx = 0; dx < 3; dx++) {
                        int ww = w + (dx - 1) * d;
                        if ((unsigned)ww < 128u) {
                            float2 v = *(const float2*)(rp[t3] + ((size_t)ww << 6));
                            a0 += v.x * tap0[t3][dx];
                            a1 += v.y * tap1[t3][dx];
                        }
                    }
                }
            }
            unsigned ph, pl; bsplit(a0, a1, ph, pl);
            sUhi[p*USTR + pc] = ph; sUlo[p*USTR + pc] = pl;
        }
    }
    __syncthreads();

    // ---- mma mapping ----
    int warp = tid >> 5, lane = tid & 31;
    int g  = lane >> 2;   // 0..7
    int tg = lane & 3;    // 0..3
    int m0 = (warp & 1) << 4;
    int n0 = (warp >> 1) << 4;

    // ---- phase 2: H = GELU(U @ W1 + b1), bf16 split (3 mma terms) ----
    float aM[2][4] = {{0,0,0,0},{0,0,0,0}};
    float aC[2][4] = {{0,0,0,0},{0,0,0,0}};

    for (int cc = 0; cc < 10; cc++) {
        __syncthreads();
        {
            int pc0 = cc << 5;
            #pragma unroll
            for (int it = tid; it < 1024; it += THREADS) {
                int arr = it >> 9, r = (it >> 4) & 31, q = it & 15;
                const uint4* src = (const uint4*)((arr ? gW1lo : gW1hi) + ((pc0 + r) << 6)) + q;
                uint4* dst = (uint4*)((arr ? sWlo : sWhi) + r * WSTR) + q;
                *dst = *src;
            }
        }
        __syncthreads();
        #pragma unroll
        for (int ks = 0; ks < 4; ks++) {
            int base = (m0 + g) * USTR + (cc << 5) + (ks << 3) + tg;
            unsigned ah0 = sUhi[base],              ah2 = sUhi[base + 4];
            unsigned ah1 = sUhi[base + 8*USTR],     ah3 = sUhi[base + 8*USTR + 4];
            unsigned al0 = sUlo[base],              al2 = sUlo[base + 4];
            unsigned al1 = sUlo[base + 8*USTR],     al3 = sUlo[base + 8*USTR + 4];
            #pragma unroll
            for (int nt = 0; nt < 2; nt++) {
                int bidx = ((ks << 3) + tg) * WSTR + n0 + (nt << 3) + g;
                unsigned bh0 = sWhi[bidx], bh1 = sWhi[bidx + 4*WSTR];
                unsigned bl0 = sWlo[bidx], bl1 = sWlo[bidx + 4*WSTR];
                mma_bf16(aM[nt], ah0, ah1, ah2, ah3, bh0, bh1);
                mma_bf16(aC[nt], al0, al1, al2, al3, bh0, bh1);
                mma_bf16(aC[nt], ah0, ah1, ah2, ah3, bl0, bl1);
            }
        }
    }

    // bias + GELU -> packed H
    #pragma unroll
    for (int nt = 0; nt < 2; nt++) {
        float2 bb = *(const float2*)(b1 + n0 + (nt << 3) + (tg << 1));
        float v0 = gelu(aM[nt][0] + aC[nt][0] + bb.x);
        float v1 = gelu(aM[nt][1] + aC[nt][1] + bb.y);
        float v2 = gelu(aM[nt][2] + aC[nt][2] + bb.x);
        float v3 = gelu(aM[nt][3] + aC[nt][3] + bb.y);
        int hpc = (n0 >> 1) + (nt << 2) + tg;
        unsigned ph, pl;
        bsplit(v0, v1, ph, pl);
        sHhi[(m0 + g) * HSTR + hpc] = ph; sHlo[(m0 + g) * HSTR + hpc] = pl;
        bsplit(v2, v3, ph, pl);
        sHhi[(m0 + g + 8) * HSTR + hpc] = ph; sHlo[(m0 + g + 8) * HSTR + hpc] = pl;
    }
    __syncthreads();

    // stage W2 (whole, 32 pair-rows)
    #pragma unroll
    for (int it = tid; it < 1024; it += THREADS) {
        int arr = it >> 9, r = (it >> 4) & 31, q = it & 15;
        const uint4* src = (const uint4*)((arr ? gW2lo : gW2hi) + (r << 6)) + q;
        uint4* dst = (uint4*)((arr ? sWlo : sWhi) + r * WSTR) + q;
        *dst = *src;
    }
    __syncthreads();

    // ---- phase 3: y = H @ W2 + b2 ----
    float oM[2][4] = {{0,0,0,0},{0,0,0,0}};
    float oC[2][4] = {{0,0,0,0},{0,0,0,0}};
    #pragma unroll
    for (int ks = 0; ks < 4; ks++) {
        int base = (m0 + g) * HSTR + (ks << 3) + tg;
        unsigned ah0 = sHhi[base],            ah2 = sHhi[base + 4];
        unsigned ah1 = sHhi[base + 8*HSTR],   ah3 = sHhi[base + 8*HSTR + 4];
        unsigned al0 = sHlo[base],            al2 = sHlo[base + 4];
        unsigned al1 = sHlo[base + 8*HSTR],   al3 = sHlo[base + 8*HSTR + 4];
        #pragma unroll
        for (int nt = 0; nt < 2; nt++) {
            int bidx = ((ks << 3) + tg) * WSTR + n0 + (nt << 3) + g;
            unsigned bh0 = sWhi[bidx], bh1 = sWhi[bidx + 4*WSTR];
            unsigned bl0 = sWlo[bidx], bl1 = sWlo[bidx + 4*WSTR];
            mma_bf16(oM[nt], ah0, ah1, ah2, ah3, bh0, bh1);
            mma_bf16(oC[nt], al0, al1, al2, al3, bh0, bh1);
            mma_bf16(oC[nt], ah0, ah1, ah2, ah3, bl0, bl1);
        }
    }

    // bias + store
    const size_t pixbase = (((size_t)(b << 7) + h) << 7) + w0;
    #pragma unroll
    for (int nt = 0; nt < 2; nt++) {
        int col = n0 + (nt << 3) + (tg << 1);
        float2 bb = *(const float2*)(b2 + col);
        *(float2*)(y + ((pixbase + m0 + g) << 6) + col) =
            make_float2(oM[nt][0] + oC[nt][0] + bb.x, oM[nt][1] + oC[nt][1] + bb.y);
        *(float2*)(y + ((pixbase + m0 + g + 8) << 6) + col) =
            make_float2(oM[nt][2] + oC[nt][2] + bb.x, oM[nt][3] + oC[nt][3] + bb.y);
    }
}

// ---------------------------------------------------------------------------
extern "C" void kernel_launch(void* const* d_in, const int* in_sizes, int n_in,
                              void* d_out, int out_size)
{
    const float* x   = (const float*)d_in[0];
    const float* c   = (const float*)d_in[1];
    const float* Wv  = (const float*)d_in[6];
    const float* bv  = (const float*)d_in[7];
    const float* Wo  = (const float*)d_in[8];
    const float* bo  = (const float*)d_in[9];
    const float* lng = (const float*)d_in[10];
    const float* lnb = (const float*)d_in[11];
    const float* pk  = (const float*)d_in[12];
    const float* W1  = (const float*)d_in[13];
    const float* b1  = (const float*)d_in[14];
    const float* W2  = (const float*)d_in[15];
    const float* b2  = (const float*)d_in[16];

    float* y     = (float*)d_out;
    float* outc2 = y + (size_t)BB * 128 * 128 * CH;

    prep_kernel<<<80, THREADS>>>(W1, W2);
    ctx_kernel<<<1, 256>>>(c, Wv, bv, Wo, bo, lng, lnb, outc2);

    cudaFuncSetAttribute(nca_kernel, cudaFuncAttributeMaxDynamicSharedMemorySize, SMEM_BYTES);
    nca_kernel<<<4096, THREADS, SMEM_BYTES>>>(x, pk, b1, b2, y);
}